// round 5
// baseline (speedup 1.0000x reference)
#include <cuda_runtime.h>
#include <cstdint>

#define NN   50000
#define NE   800000
#define DIN  96
#define DH   128
#define DOUT 16

typedef unsigned long long ull;

// ---------------- scratch (no allocations allowed) ----------------
__device__ __align__(16) float g_agg1[NN * DIN];   // sum of x[src] at dst
__device__ float g_deg   [NN];                     // in-degree by dst
__device__ __align__(16) float g_r   [NN * 32];    // [p | q] = h @ [W2_l | W2_r]
__device__ __align__(16) float g_agg2[NN * DOUT];  // sum of p[src] at dst
__device__ int   g_cnt   [NN];                     // out-degree histogram (by src)
__device__ int   g_rowptr[NN + 1];                 // CSR (by src) row pointers
__device__ int   g_cursor[NN];
__device__ int   g_edst  [NE];                     // dst ids grouped by src
__device__ int   g_is64;

// ---------------- f32x2 packed helpers (sm_100+) ----------------
__device__ __forceinline__ ull pk(float a, float b) {
    ull r; asm("mov.b64 %0, {%1,%2};" : "=l"(r) : "f"(a), "f"(b)); return r;
}
__device__ __forceinline__ float2 upk(ull a) {
    float2 f; asm("mov.b64 {%0,%1}, %2;" : "=f"(f.x), "=f"(f.y) : "l"(a)); return f;
}
__device__ __forceinline__ ull fma2(ull a, ull b, ull c) {
    ull d; asm("fma.rn.f32x2 %0, %1, %2, %3;" : "=l"(d) : "l"(a), "l"(b), "l"(c)); return d;
}
__device__ __forceinline__ void red4(float* g, float4 v) {
    asm volatile("red.global.add.v4.f32 [%0], {%1,%2,%3,%4};"
                 :: "l"(g), "f"(v.x), "f"(v.y), "f"(v.z), "f"(v.w) : "memory");
}

// ---------------- dtype detection for edge_index ----------------
__global__ void k_detect(const int* __restrict__ ei) {
    int all0 = 1;
#pragma unroll 1
    for (int i = 1; i < 256; i += 2) all0 &= (ei[i] == 0);
    g_is64 = all0;
}

// ---------------- histogram by src  +  degree by dst ----------------
__global__ void k_hist(const int* __restrict__ ei32,
                       const long long* __restrict__ ei64) {
    int e = blockIdx.x * blockDim.x + threadIdx.x;
    if (e >= NE) return;
    int src, dst;
    if (g_is64) { src = (int)ei64[e]; dst = (int)ei64[NE + e]; }
    else        { src = ei32[e];      dst = ei32[NE + e]; }
    atomicAdd(&g_cnt[src], 1);
    atomicAdd(&g_deg[dst], 1.0f);
}

// ---------------- single-block scan of 50k counters ----------------
__global__ void __launch_bounds__(1024) k_scan() {
    __shared__ int ssum[1024];
    const int t    = threadIdx.x;
    const int base = t * 49;

    int run = 0;
#pragma unroll 7
    for (int i = 0; i < 49; i++) {
        int idx = base + i;
        run += (idx < NN) ? g_cnt[idx] : 0;
    }
    ssum[t] = run;
    __syncthreads();
    for (int off = 1; off < 1024; off <<= 1) {
        int v = (t >= off) ? ssum[t - off] : 0;
        __syncthreads();
        ssum[t] += v;
        __syncthreads();
    }
    int excl = (t == 0) ? 0 : ssum[t - 1];
#pragma unroll 1
    for (int i = 0; i < 49; i++) {
        int idx = base + i;
        if (idx <= NN) {
            g_rowptr[idx] = excl;
            if (idx < NN) g_cursor[idx] = excl;
        }
        if (idx < NN) excl += g_cnt[idx];
    }
}

// ---------------- scatter dst ids grouped by src ----------------
__global__ void k_scatter(const int* __restrict__ ei32,
                          const long long* __restrict__ ei64) {
    int e = blockIdx.x * blockDim.x + threadIdx.x;
    if (e >= NE) return;
    int src, dst;
    if (g_is64) { src = (int)ei64[e]; dst = (int)ei64[NE + e]; }
    else        { src = ei32[e];      dst = ei32[NE + e]; }
    int pos = atomicAdd(&g_cursor[src], 1);
    g_edst[pos] = dst;
}

// ---------------- layer-1 push-aggregation: warp per src, L1-resident row ----------------
__global__ void __launch_bounds__(256) k_aggx(const float* __restrict__ x) {
    const int lane = threadIdx.x & 31;
    const int n    = blockIdx.x * 8 + (threadIdx.x >> 5);
    if (n >= NN) return;
    const int beg = g_rowptr[n];
    const int m   = (g_rowptr[n + 1] - beg) * 24;
    const float4* xr = (const float4*)(x + (size_t)n * DIN);

#pragma unroll 1
    for (int idx = lane; idx < m; idx += 32) {
        int e = idx / 24;
        int c = idx - e * 24;
        int dst = g_edst[beg + e];
        red4(g_agg1 + (size_t)dst * DIN + c * 4, xr[c]);
    }
}

// ---------------- fused layer-1 GEMM + layer-2 projection (unchanged, R2) ----------------
__global__ void __launch_bounds__(128) k_fused(
        const float* __restrict__ x,
        const float* __restrict__ W1l,
        const float* __restrict__ b1,
        const float* __restrict__ W1r,
        const float* __restrict__ W2l,
        const float* __restrict__ W2r) {

    __shared__ ulonglong2 aspv[DIN][2];
    __shared__ ulonglong2 xspv[DIN][2];
    __shared__ ull        hsT [4][DH];
    __shared__ float      wsT [32][132];
    __shared__ float      inv [8];

    const int tid  = threadIdx.x;
    const int row0 = blockIdx.x * 8;

    if (tid < 8) inv[tid] = 1.0f / fmaxf(g_deg[row0 + tid], 1.0f);

    for (int i = tid; i < DH * DOUT; i += 128) {
        int k = i >> 4, j = i & 15;
        wsT[j][k]      = W2l[i];
        wsT[j + 16][k] = W2r[i];
    }
    __syncthreads();

    {
        float* aspf = (float*)aspv;
        float* xspf = (float*)xspv;
        for (int idx = tid; idx < 8 * DIN; idx += 128) {
            int r = idx / DIN, k = idx - r * DIN;
            size_t g = (size_t)(row0 + r) * DIN + k;
            aspf[k * 8 + r] = g_agg1[g] * inv[r];
            xspf[k * 8 + r] = x[g];
        }
    }
    __syncthreads();

    const int j = tid;
    ull acc[4];
    {
        float bj = b1[j];
        ull b2p = pk(bj, bj);
#pragma unroll
        for (int p = 0; p < 4; p++) acc[p] = b2p;
    }

#pragma unroll 2
    for (int k = 0; k < DIN; k++) {
        float wl = W1l[k * DH + j];
        float wr = W1r[k * DH + j];
        ull wl2 = pk(wl, wl);
        ull wr2 = pk(wr, wr);
#pragma unroll
        for (int i = 0; i < 2; i++) {
            ulonglong2 av = aspv[k][i];
            ulonglong2 xv = xspv[k][i];
            acc[2*i]   = fma2(av.x, wl2, acc[2*i]);
            acc[2*i]   = fma2(xv.x, wr2, acc[2*i]);
            acc[2*i+1] = fma2(av.y, wl2, acc[2*i+1]);
            acc[2*i+1] = fma2(xv.y, wr2, acc[2*i+1]);
        }
    }

#pragma unroll
    for (int p = 0; p < 4; p++) {
        float2 f = upk(acc[p]);
        hsT[p][j] = pk(fmaxf(f.x, 0.0f), fmaxf(f.y, 0.0f));
    }
    __syncthreads();

    const int c  = tid & 31;
    const int rp = tid >> 5;
    const ulonglong2* hrow = (const ulonglong2*)hsT[rp];
    const float4*     wrow = (const float4*)wsT[c];

    ull acc2 = 0;
#pragma unroll 8
    for (int k4 = 0; k4 < DH / 4; k4++) {
        float4     w4  = wrow[k4];
        ulonglong2 h01 = hrow[2*k4];
        ulonglong2 h23 = hrow[2*k4+1];
        acc2 = fma2(h01.x, pk(w4.x, w4.x), acc2);
        acc2 = fma2(h01.y, pk(w4.y, w4.y), acc2);
        acc2 = fma2(h23.x, pk(w4.z, w4.z), acc2);
        acc2 = fma2(h23.y, pk(w4.w, w4.w), acc2);
    }
    float2 o2 = upk(acc2);
    g_r[(size_t)(row0 + 2*rp)     * 32 + c] = o2.x;
    g_r[(size_t)(row0 + 2*rp + 1) * 32 + c] = o2.y;
}

// ---------------- layer-2 push-aggregation: warp per src ----------------
__global__ void __launch_bounds__(256) k_aggp(void) {
    const int lane = threadIdx.x & 31;
    const int n    = blockIdx.x * 8 + (threadIdx.x >> 5);
    if (n >= NN) return;
    const int beg = g_rowptr[n];
    const int m   = (g_rowptr[n + 1] - beg) * 4;
    const float4* pr = (const float4*)(g_r + (size_t)n * 32);   // p = first 16 floats

#pragma unroll 1
    for (int idx = lane; idx < m; idx += 32) {
        int e = idx >> 2;
        int c = idx & 3;
        int dst = g_edst[beg + e];
        red4(g_agg2 + (size_t)dst * DOUT + c * 4, pr[c]);
    }
}

// ---------------- epilogue: softmax(agg2/deg + b2 + q) ----------------
__global__ void k_finalize(const float* __restrict__ b2,
                           float* __restrict__ out) {
    int row = blockIdx.x * blockDim.x + threadIdx.x;
    if (row >= NN) return;
    float inv = 1.0f / fmaxf(g_deg[row], 1.0f);

    float v[DOUT];
    float mx = -1e30f;
#pragma unroll
    for (int j = 0; j < DOUT; j++) {
        v[j] = g_agg2[(size_t)row * DOUT + j] * inv + b2[j]
             + g_r[(size_t)row * 32 + 16 + j];
        mx = fmaxf(mx, v[j]);
    }
    float s = 0.f;
#pragma unroll
    for (int j = 0; j < DOUT; j++) {
        v[j] = __expf(v[j] - mx);
        s += v[j];
    }
    float is = 1.0f / s;
#pragma unroll
    for (int j = 0; j < DOUT; j++)
        out[(size_t)row * DOUT + j] = v[j] * is;
}

// ---------------- launch ----------------
extern "C" void kernel_launch(void* const* d_in, const int* in_sizes, int n_in,
                              void* d_out, int out_size) {
    const float*     x    = (const float*)d_in[0];
    const int*       ei32 = (const int*)d_in[1];
    const long long* ei64 = (const long long*)d_in[1];
    const float*     W1l  = (const float*)d_in[2];
    const float*     b1   = (const float*)d_in[3];
    const float*     W1r  = (const float*)d_in[4];
    const float*     W2l  = (const float*)d_in[5];
    const float*     b2   = (const float*)d_in[6];
    const float*     W2r  = (const float*)d_in[7];
    float* out = (float*)d_out;

    void *agg1p, *degp, *agg2p, *cntp;
    cudaGetSymbolAddress(&agg1p, g_agg1);
    cudaGetSymbolAddress(&degp,  g_deg);
    cudaGetSymbolAddress(&agg2p, g_agg2);
    cudaGetSymbolAddress(&cntp,  g_cnt);
    cudaMemsetAsync(agg1p, 0, sizeof(float) * NN * DIN, 0);
    cudaMemsetAsync(degp,  0, sizeof(float) * NN, 0);
    cudaMemsetAsync(agg2p, 0, sizeof(float) * NN * DOUT, 0);
    cudaMemsetAsync(cntp,  0, sizeof(int) * NN, 0);

    k_detect  <<<1, 1>>>(ei32);
    k_hist    <<<(NE + 255) / 256, 256>>>(ei32, ei64);
    k_scan    <<<1, 1024>>>();
    k_scatter <<<(NE + 255) / 256, 256>>>(ei32, ei64);
    k_aggx    <<<(NN + 7) / 8, 256>>>(x);
    k_fused   <<<NN / 8, 128>>>(x, W1l, b1, W1r, W2l, W2r);
    k_aggp    <<<(NN + 7) / 8, 256>>>();
    k_finalize<<<(NN + 127) / 128, 128>>>(b2, out);
}

// round 6
// speedup vs baseline: 1.2715x; 1.2715x over previous
#include <cuda_runtime.h>
#include <cstdint>

#define NN   50000
#define NE   800000
#define DIN  96
#define DH   128
#define DOUT 16

typedef unsigned long long ull;

// ---------------- scratch (no allocations allowed) ----------------
__device__ __align__(16) float g_agg1[NN * DIN];   // sum of x[src] at dst
__device__ float g_deg [NN];
__device__ __align__(16) float g_hB  [NN * DH];    // x @ W1_r + b1
__device__ __align__(16) float g_r   [NN * 32];    // [p | q] = h @ [W2_l | W2_r]
__device__ __align__(16) float g_agg2[NN * DOUT];  // sum of p[src] at dst
__device__ int   g_is64;

// ---------------- f32x2 packed helpers (sm_100+) ----------------
__device__ __forceinline__ ull pk(float a, float b) {
    ull r; asm("mov.b64 %0, {%1,%2};" : "=l"(r) : "f"(a), "f"(b)); return r;
}
__device__ __forceinline__ float2 upk(ull a) {
    float2 f; asm("mov.b64 {%0,%1}, %2;" : "=f"(f.x), "=f"(f.y) : "l"(a)); return f;
}
__device__ __forceinline__ ull fma2(ull a, ull b, ull c) {
    ull d; asm("fma.rn.f32x2 %0, %1, %2, %3;" : "=l"(d) : "l"(a), "l"(b), "l"(c)); return d;
}

// ---------------- dtype detection for edge_index ----------------
__global__ void k_detect(const int* __restrict__ ei) {
    if (threadIdx.x == 0) {
        int all0 = 1;
#pragma unroll 1
        for (int i = 1; i < 256; i += 2) all0 &= (ei[i] == 0);
        g_is64 = all0;
    }
}

// ---------------- layer-1 edge aggregation + degree (R2 champion) ----------------
__global__ void k_agg_x(const int* __restrict__ ei32,
                        const long long* __restrict__ ei64,
                        const float* __restrict__ x) {
    int gid = blockIdx.x * blockDim.x + threadIdx.x;
    if (gid >= NE * 24) return;
    int e = gid / 24;
    int c = gid - e * 24;
    int src, dst;
    if (g_is64) { src = (int)ei64[e]; dst = (int)ei64[NE + e]; }
    else        { src = ei32[e];      dst = ei32[NE + e]; }

    const float4 v = ((const float4*)(x + (size_t)src * DIN))[c];
    float4* o = ((float4*)(g_agg1 + (size_t)dst * DIN)) + c;
    asm volatile("red.global.add.v4.f32 [%0], {%1,%2,%3,%4};"
                 :: "l"(o), "f"(v.x), "f"(v.y), "f"(v.z), "f"(v.w) : "memory");
    if (c == 0) atomicAdd(&g_deg[dst], 1.0f);
}

// ---------------- independent half: g_hB = x @ W1_r + b1  (overlaps agg_x) ----------------
__global__ void __launch_bounds__(128) k_gemmB(const float* __restrict__ x,
                                               const float* __restrict__ W1r,
                                               const float* __restrict__ b1) {
    __shared__ ulonglong2 xspv[DIN][2];

    const int tid  = threadIdx.x;
    const int row0 = blockIdx.x * 8;

    {
        float* xspf = (float*)xspv;
        for (int idx = tid; idx < 8 * DIN; idx += 128) {
            int r = idx / DIN, k = idx - r * DIN;
            xspf[k * 8 + r] = x[(size_t)(row0 + r) * DIN + k];
        }
    }
    __syncthreads();

    const int j = tid;
    ull acc[4];
    {
        float bj = b1[j];
        ull bp = pk(bj, bj);
#pragma unroll
        for (int p = 0; p < 4; p++) acc[p] = bp;
    }

#pragma unroll 4
    for (int k = 0; k < DIN; k++) {
        float wr = W1r[k * DH + j];
        ull wr2 = pk(wr, wr);
#pragma unroll
        for (int i = 0; i < 2; i++) {
            ulonglong2 xv = xspv[k][i];
            acc[2*i]   = fma2(xv.x, wr2, acc[2*i]);
            acc[2*i+1] = fma2(xv.y, wr2, acc[2*i+1]);
        }
    }

#pragma unroll
    for (int p = 0; p < 4; p++) {
        float2 f = upk(acc[p]);
        g_hB[(size_t)(row0 + 2*p)     * DH + j] = f.x;
        g_hB[(size_t)(row0 + 2*p + 1) * DH + j] = f.y;
    }
}

// ---------------- dependent half: h = relu(agg1/deg @ W1_l + hB); r = h @ [W2_l|W2_r] ----------------
__global__ void __launch_bounds__(128) k_fusedA(
        const float* __restrict__ W1l,
        const float* __restrict__ W2l,
        const float* __restrict__ W2r) {

    __shared__ ulonglong2 aspv[DIN][2];
    __shared__ ull        hsT [4][DH];
    __shared__ float      wsT [32][132];
    __shared__ float      inv [8];

    const int tid  = threadIdx.x;
    const int row0 = blockIdx.x * 8;

    if (tid < 8) inv[tid] = 1.0f / fmaxf(g_deg[row0 + tid], 1.0f);

    for (int i = tid; i < DH * DOUT; i += 128) {
        int k = i >> 4, j = i & 15;
        wsT[j][k]      = W2l[i];
        wsT[j + 16][k] = W2r[i];
    }
    __syncthreads();

    {
        float* aspf = (float*)aspv;
        for (int idx = tid; idx < 8 * DIN; idx += 128) {
            int r = idx / DIN, k = idx - r * DIN;
            aspf[k * 8 + r] = g_agg1[(size_t)(row0 + r) * DIN + k] * inv[r];
        }
    }
    __syncthreads();

    const int j = tid;
    ull acc[4] = {0, 0, 0, 0};

#pragma unroll 4
    for (int k = 0; k < DIN; k++) {
        float wl = W1l[k * DH + j];
        ull wl2 = pk(wl, wl);
#pragma unroll
        for (int i = 0; i < 2; i++) {
            ulonglong2 av = aspv[k][i];
            acc[2*i]   = fma2(av.x, wl2, acc[2*i]);
            acc[2*i+1] = fma2(av.y, wl2, acc[2*i+1]);
        }
    }

    // add precomputed x@W1_r + b1, relu, stash packed h
#pragma unroll
    for (int p = 0; p < 4; p++) {
        float hb0 = g_hB[(size_t)(row0 + 2*p)     * DH + j];
        float hb1 = g_hB[(size_t)(row0 + 2*p + 1) * DH + j];
        float2 f = upk(acc[p]);
        hsT[p][j] = pk(fmaxf(f.x + hb0, 0.0f), fmaxf(f.y + hb1, 0.0f));
    }
    __syncthreads();

    const int c  = tid & 31;
    const int rp = tid >> 5;
    const ulonglong2* hrow = (const ulonglong2*)hsT[rp];
    const float4*     wrow = (const float4*)wsT[c];

    ull acc2 = 0;
#pragma unroll 8
    for (int k4 = 0; k4 < DH / 4; k4++) {
        float4     w4  = wrow[k4];
        ulonglong2 h01 = hrow[2*k4];
        ulonglong2 h23 = hrow[2*k4+1];
        acc2 = fma2(h01.x, pk(w4.x, w4.x), acc2);
        acc2 = fma2(h01.y, pk(w4.y, w4.y), acc2);
        acc2 = fma2(h23.x, pk(w4.z, w4.z), acc2);
        acc2 = fma2(h23.y, pk(w4.w, w4.w), acc2);
    }
    float2 o2 = upk(acc2);
    g_r[(size_t)(row0 + 2*rp)     * 32 + c] = o2.x;
    g_r[(size_t)(row0 + 2*rp + 1) * 32 + c] = o2.y;
}

// ---------------- layer-2 edge aggregation (R2 champion) ----------------
__global__ void k_agg_p(const int* __restrict__ ei32,
                        const long long* __restrict__ ei64) {
    int gid = blockIdx.x * blockDim.x + threadIdx.x;
    if (gid >= NE * 4) return;
    int e = gid >> 2;
    int c = gid & 3;
    int src, dst;
    if (g_is64) { src = (int)ei64[e]; dst = (int)ei64[NE + e]; }
    else        { src = ei32[e];      dst = ei32[NE + e]; }

    const float4 v = ((const float4*)(g_r + (size_t)src * 32))[c];
    float4* o = ((float4*)(g_agg2 + (size_t)dst * DOUT)) + c;
    asm volatile("red.global.add.v4.f32 [%0], {%1,%2,%3,%4};"
                 :: "l"(o), "f"(v.x), "f"(v.y), "f"(v.z), "f"(v.w) : "memory");
}

// ---------------- epilogue: softmax(agg2/deg + b2 + q) ----------------
__global__ void k_finalize(const float* __restrict__ b2,
                           float* __restrict__ out) {
    int row = blockIdx.x * blockDim.x + threadIdx.x;
    if (row >= NN) return;
    float inv = 1.0f / fmaxf(g_deg[row], 1.0f);

    float v[DOUT];
    float mx = -1e30f;
#pragma unroll
    for (int j = 0; j < DOUT; j++) {
        v[j] = g_agg2[(size_t)row * DOUT + j] * inv + b2[j]
             + g_r[(size_t)row * 32 + 16 + j];
        mx = fmaxf(mx, v[j]);
    }
    float s = 0.f;
#pragma unroll
    for (int j = 0; j < DOUT; j++) {
        v[j] = __expf(v[j] - mx);
        s += v[j];
    }
    float is = 1.0f / s;
#pragma unroll
    for (int j = 0; j < DOUT; j++)
        out[(size_t)row * DOUT + j] = v[j] * is;
}

// ---------------- launch ----------------
extern "C" void kernel_launch(void* const* d_in, const int* in_sizes, int n_in,
                              void* d_out, int out_size) {
    const float*     x    = (const float*)d_in[0];
    const int*       ei32 = (const int*)d_in[1];
    const long long* ei64 = (const long long*)d_in[1];
    const float*     W1l  = (const float*)d_in[2];
    const float*     b1   = (const float*)d_in[3];
    const float*     W1r  = (const float*)d_in[4];
    const float*     W2l  = (const float*)d_in[5];
    const float*     b2   = (const float*)d_in[6];
    const float*     W2r  = (const float*)d_in[7];
    float* out = (float*)d_out;

    // one-time host resources (no device memory; identical launches every call)
    static cudaStream_t s1 = nullptr;
    static cudaEvent_t  evFork = nullptr, evJoin = nullptr;
    if (!s1) {
        cudaStreamCreateWithFlags(&s1, cudaStreamNonBlocking);
        cudaEventCreateWithFlags(&evFork, cudaEventDisableTiming);
        cudaEventCreateWithFlags(&evJoin, cudaEventDisableTiming);
    }

    void *agg1p, *degp, *agg2p;
    cudaGetSymbolAddress(&agg1p, g_agg1);
    cudaGetSymbolAddress(&degp,  g_deg);
    cudaGetSymbolAddress(&agg2p, g_agg2);

    // fork: independent GEMM half on side stream
    cudaEventRecord(evFork, 0);
    cudaStreamWaitEvent(s1, evFork, 0);
    k_gemmB<<<NN / 8, 128, 0, s1>>>(x, W1r, b1);
    cudaEventRecord(evJoin, s1);

    // main stream: zero + detect + aggregation (LTS-bound, overlaps gemmB)
    cudaMemsetAsync(agg1p, 0, sizeof(float) * NN * DIN, 0);
    cudaMemsetAsync(degp,  0, sizeof(float) * NN, 0);
    cudaMemsetAsync(agg2p, 0, sizeof(float) * NN * DOUT, 0);
    k_detect<<<1, 32>>>(ei32);
    k_agg_x<<<(NE * 24 + 255) / 256, 256>>>(ei32, ei64, x);

    // join, then dependent half + layer 2
    cudaStreamWaitEvent(0, evJoin, 0);
    k_fusedA  <<<NN / 8, 128>>>(W1l, W2l, W2r);
    k_agg_p   <<<(NE * 4 + 255) / 256, 256>>>(ei32, ei64);
    k_finalize<<<(NN + 127) / 128, 128>>>(b2, out);
}

// round 7
// speedup vs baseline: 1.4124x; 1.1108x over previous
#include <cuda_runtime.h>
#include <cstdint>

#define NN   50000
#define NE   800000
#define DIN  96
#define DH   128
#define DOUT 16

typedef unsigned long long ull;

// ---------------- scratch (no allocations allowed) ----------------
__device__ __align__(16) float g_agg1[NN * DIN];   // sum of x[src] at dst
__device__ float g_deg [NN];
__device__ __align__(16) float g_r   [NN * 32];    // [p | q] = h @ [W2_l | W2_r]
__device__ __align__(16) float g_agg2[NN * DOUT];  // sum of p[src] at dst
__device__ int   g_is64;

// ---------------- f32x2 packed helpers (sm_100+) ----------------
__device__ __forceinline__ ull pk(float a, float b) {
    ull r; asm("mov.b64 %0, {%1,%2};" : "=l"(r) : "f"(a), "f"(b)); return r;
}
__device__ __forceinline__ float2 upk(ull a) {
    float2 f; asm("mov.b64 {%0,%1}, %2;" : "=f"(f.x), "=f"(f.y) : "l"(a)); return f;
}
__device__ __forceinline__ ull fma2(ull a, ull b, ull c) {
    ull d; asm("fma.rn.f32x2 %0, %1, %2, %3;" : "=l"(d) : "l"(a), "l"(b), "l"(c)); return d;
}

// ---------------- dtype detection for edge_index ----------------
__global__ void k_detect(const int* __restrict__ ei) {
    if (threadIdx.x == 0) {
        int all0 = 1;
#pragma unroll 1
        for (int i = 1; i < 256; i += 2) all0 &= (ei[i] == 0);
        g_is64 = all0;
    }
}

// ---------------- layer-1 edge aggregation + degree (R2 champion) ----------------
__global__ void k_agg_x(const int* __restrict__ ei32,
                        const long long* __restrict__ ei64,
                        const float* __restrict__ x) {
    int gid = blockIdx.x * blockDim.x + threadIdx.x;
    if (gid >= NE * 24) return;
    int e = gid / 24;
    int c = gid - e * 24;
    int src, dst;
    if (g_is64) { src = (int)ei64[e]; dst = (int)ei64[NE + e]; }
    else        { src = ei32[e];      dst = ei32[NE + e]; }

    const float4 v = ((const float4*)(x + (size_t)src * DIN))[c];
    float4* o = ((float4*)(g_agg1 + (size_t)dst * DIN)) + c;
    asm volatile("red.global.add.v4.f32 [%0], {%1,%2,%3,%4};"
                 :: "l"(o), "f"(v.x), "f"(v.y), "f"(v.z), "f"(v.w) : "memory");
    if (c == 0) atomicAdd(&g_deg[dst], 1.0f);
}

// ---------------- fused GEMMs, 16 rows per block ----------------
// stage A: h[16][128] = relu((agg1/deg)@W1_l + b1 + x@W1_r)
// stage B: r[16][32]  = h @ [W2_l | W2_r]
__global__ void __launch_bounds__(128) k_fused(
        const float* __restrict__ x,
        const float* __restrict__ W1l,
        const float* __restrict__ b1,
        const float* __restrict__ W1r,
        const float* __restrict__ W2l,
        const float* __restrict__ W2r) {

    __shared__ ulonglong2 aspv[DIN][4];      // 6 KB   [k][quad] rows packed
    __shared__ ulonglong2 xspv[DIN][4];      // 6 KB
    __shared__ ull        hsT [8][DH];       // 8 KB   [row-pair][k]
    __shared__ float      wsT [32][132];     // 16.5 KB [out col][k] (padded)
    __shared__ float      inv [16];

    const int tid  = threadIdx.x;
    const int row0 = blockIdx.x * 16;

    if (tid < 16) inv[tid] = 1.0f / fmaxf(g_deg[row0 + tid], 1.0f);

    // W2 = [W2_l | W2_r] transposed into wsT[c][k]
    for (int i = tid; i < DH * DOUT; i += 128) {
        int k = i >> 4, j = i & 15;
        wsT[j][k]      = W2l[i];
        wsT[j + 16][k] = W2r[i];
    }
    __syncthreads();   // inv visible

    // stage rows: [k][r] packed layout, 16 rows
    {
        float* aspf = (float*)aspv;
        float* xspf = (float*)xspv;
        for (int idx = tid; idx < 16 * DIN; idx += 128) {
            int r = idx / DIN, k = idx - r * DIN;
            size_t g = (size_t)(row0 + r) * DIN + k;
            aspf[k * 16 + r] = g_agg1[g] * inv[r];
            xspf[k * 16 + r] = x[g];
        }
    }
    __syncthreads();

    // ---- stage A: thread = output column j, 8 row-pair accumulators ----
    const int j = tid;
    ull acc[8];
    {
        float bj = b1[j];
        ull bp = pk(bj, bj);
#pragma unroll
        for (int p = 0; p < 8; p++) acc[p] = bp;
    }

#pragma unroll 2
    for (int k = 0; k < DIN; k++) {
        float wl = W1l[k * DH + j];
        float wr = W1r[k * DH + j];
        ull wl2 = pk(wl, wl);
        ull wr2 = pk(wr, wr);
#pragma unroll
        for (int i = 0; i < 4; i++) {
            ulonglong2 av = aspv[k][i];
            ulonglong2 xv = xspv[k][i];
            acc[2*i]   = fma2(av.x, wl2, acc[2*i]);
            acc[2*i]   = fma2(xv.x, wr2, acc[2*i]);
            acc[2*i+1] = fma2(av.y, wl2, acc[2*i+1]);
            acc[2*i+1] = fma2(xv.y, wr2, acc[2*i+1]);
        }
    }

    // relu + stash packed h (row-pair p = rows 2p, 2p+1)
#pragma unroll
    for (int p = 0; p < 8; p++) {
        float2 f = upk(acc[p]);
        hsT[p][j] = pk(fmaxf(f.x, 0.0f), fmaxf(f.y, 0.0f));
    }
    __syncthreads();

    // ---- stage B: thread = (col c, row-pair rp4) handling pairs rp4 and rp4+4 ----
    const int c   = tid & 31;
    const int rp4 = tid >> 5;
    const ulonglong2* hrow0 = (const ulonglong2*)hsT[rp4];
    const ulonglong2* hrow1 = (const ulonglong2*)hsT[rp4 + 4];
    const float4*     wrow  = (const float4*)wsT[c];

    ull a0 = 0, a1 = 0;
#pragma unroll 8
    for (int k4 = 0; k4 < DH / 4; k4++) {
        float4     w4 = wrow[k4];
        ull wx = pk(w4.x, w4.x), wy = pk(w4.y, w4.y);
        ull wz = pk(w4.z, w4.z), ww = pk(w4.w, w4.w);
        ulonglong2 p01 = hrow0[2*k4];
        ulonglong2 p23 = hrow0[2*k4+1];
        ulonglong2 q01 = hrow1[2*k4];
        ulonglong2 q23 = hrow1[2*k4+1];
        a0 = fma2(p01.x, wx, a0);
        a1 = fma2(q01.x, wx, a1);
        a0 = fma2(p01.y, wy, a0);
        a1 = fma2(q01.y, wy, a1);
        a0 = fma2(p23.x, wz, a0);
        a1 = fma2(q23.x, wz, a1);
        a0 = fma2(p23.y, ww, a0);
        a1 = fma2(q23.y, ww, a1);
    }
    float2 o0 = upk(a0);
    float2 o1 = upk(a1);
    g_r[(size_t)(row0 + 2*rp4)         * 32 + c] = o0.x;
    g_r[(size_t)(row0 + 2*rp4 + 1)     * 32 + c] = o0.y;
    g_r[(size_t)(row0 + 2*(rp4+4))     * 32 + c] = o1.x;
    g_r[(size_t)(row0 + 2*(rp4+4) + 1) * 32 + c] = o1.y;
}

// ---------------- layer-2 edge aggregation (R2 champion) ----------------
__global__ void k_agg_p(const int* __restrict__ ei32,
                        const long long* __restrict__ ei64) {
    int gid = blockIdx.x * blockDim.x + threadIdx.x;
    if (gid >= NE * 4) return;
    int e = gid >> 2;
    int c = gid & 3;
    int src, dst;
    if (g_is64) { src = (int)ei64[e]; dst = (int)ei64[NE + e]; }
    else        { src = ei32[e];      dst = ei32[NE + e]; }

    const float4 v = ((const float4*)(g_r + (size_t)src * 32))[c];
    float4* o = ((float4*)(g_agg2 + (size_t)dst * DOUT)) + c;
    asm volatile("red.global.add.v4.f32 [%0], {%1,%2,%3,%4};"
                 :: "l"(o), "f"(v.x), "f"(v.y), "f"(v.z), "f"(v.w) : "memory");
}

// ---------------- epilogue: softmax(agg2/deg + b2 + q) ----------------
__global__ void k_finalize(const float* __restrict__ b2,
                           float* __restrict__ out) {
    int row = blockIdx.x * blockDim.x + threadIdx.x;
    if (row >= NN) return;
    float inv = 1.0f / fmaxf(g_deg[row], 1.0f);

    float v[DOUT];
    float mx = -1e30f;
#pragma unroll
    for (int j = 0; j < DOUT; j++) {
        v[j] = g_agg2[(size_t)row * DOUT + j] * inv + b2[j]
             + g_r[(size_t)row * 32 + 16 + j];
        mx = fmaxf(mx, v[j]);
    }
    float s = 0.f;
#pragma unroll
    for (int j = 0; j < DOUT; j++) {
        v[j] = __expf(v[j] - mx);
        s += v[j];
    }
    float is = 1.0f / s;
#pragma unroll
    for (int j = 0; j < DOUT; j++)
        out[(size_t)row * DOUT + j] = v[j] * is;
}

// ---------------- launch ----------------
extern "C" void kernel_launch(void* const* d_in, const int* in_sizes, int n_in,
                              void* d_out, int out_size) {
    const float*     x    = (const float*)d_in[0];
    const int*       ei32 = (const int*)d_in[1];
    const long long* ei64 = (const long long*)d_in[1];
    const float*     W1l  = (const float*)d_in[2];
    const float*     b1   = (const float*)d_in[3];
    const float*     W1r  = (const float*)d_in[4];
    const float*     W2l  = (const float*)d_in[5];
    const float*     b2   = (const float*)d_in[6];
    const float*     W2r  = (const float*)d_in[7];
    float* out = (float*)d_out;

    void *agg1p, *degp, *agg2p;
    cudaGetSymbolAddress(&agg1p, g_agg1);
    cudaGetSymbolAddress(&degp,  g_deg);
    cudaGetSymbolAddress(&agg2p, g_agg2);
    cudaMemsetAsync(agg1p, 0, sizeof(float) * NN * DIN, 0);
    cudaMemsetAsync(degp,  0, sizeof(float) * NN, 0);
    cudaMemsetAsync(agg2p, 0, sizeof(float) * NN * DOUT, 0);

    k_detect  <<<1, 32>>>(ei32);
    k_agg_x   <<<(NE * 24 + 255) / 256, 256>>>(ei32, ei64, x);
    k_fused   <<<(NN + 15) / 16, 128>>>(x, W1l, b1, W1r, W2l, W2r);
    k_agg_p   <<<(NE * 4 + 255) / 256, 256>>>(ei32, ei64);
    k_finalize<<<(NN + 127) / 128, 128>>>(b2, out);
}

// round 8
// speedup vs baseline: 1.7300x; 1.2249x over previous
#include <cuda_runtime.h>
#include <cstdint>

#define NN   50000
#define NE   800000
#define DIN  96
#define DH   128
#define DOUT 16
#define RB   64          // rows per fused block

typedef unsigned long long ull;

// ---------------- scratch: one merged zero-init buffer [agg1 | deg | agg2] ----------------
#define OFF_AGG1 0
#define OFF_DEG  (NN * DIN)
#define OFF_AGG2 (NN * DIN + NN)
#define ZTOTAL   (NN * DIN + NN + NN * DOUT)

__device__ __align__(16) float g_zero[ZTOTAL];
__device__ __align__(16) float g_r[NN * 32];     // [p | q] = h @ [W2_l | W2_r]
__device__ int g_is64;

// ---------------- f32x2 packed helpers (sm_100+) ----------------
__device__ __forceinline__ ull pk(float a, float b) {
    ull r; asm("mov.b64 %0, {%1,%2};" : "=l"(r) : "f"(a), "f"(b)); return r;
}
__device__ __forceinline__ float2 upk(ull a) {
    float2 f; asm("mov.b64 {%0,%1}, %2;" : "=f"(f.x), "=f"(f.y) : "l"(a)); return f;
}
__device__ __forceinline__ ull fma2(ull a, ull b, ull c) {
    ull d; asm("fma.rn.f32x2 %0, %1, %2, %3;" : "=l"(d) : "l"(a), "l"(b), "l"(c)); return d;
}
__device__ __forceinline__ ull relu2(ull a) {
    float2 f = upk(a);
    return pk(fmaxf(f.x, 0.0f), fmaxf(f.y, 0.0f));
}

// ---------------- dtype detection for edge_index ----------------
__global__ void k_detect(const int* __restrict__ ei) {
    if (threadIdx.x == 0) {
        int all0 = 1;
#pragma unroll 1
        for (int i = 1; i < 256; i += 2) all0 &= (ei[i] == 0);
        g_is64 = all0;
    }
}

// ---------------- layer-1 edge aggregation + degree ----------------
__global__ void k_agg_x(const int* __restrict__ ei32,
                        const long long* __restrict__ ei64,
                        const float* __restrict__ x) {
    int gid = blockIdx.x * blockDim.x + threadIdx.x;
    if (gid >= NE * 24) return;
    int e = gid / 24;
    int c = gid - e * 24;
    int src, dst;
    if (g_is64) { src = (int)ei64[e]; dst = (int)ei64[NE + e]; }
    else        { src = ei32[e];      dst = ei32[NE + e]; }

    const float4 v = ((const float4*)(x + (size_t)src * DIN))[c];
    float4* o = ((float4*)(g_zero + OFF_AGG1 + (size_t)dst * DIN)) + c;
    asm volatile("red.global.add.v4.f32 [%0], {%1,%2,%3,%4};"
                 :: "l"(o), "f"(v.x), "f"(v.y), "f"(v.z), "f"(v.w) : "memory");
    if (c == 0) atomicAdd(&g_zero[OFF_DEG + dst], 1.0f);
}

// ---------------- fused GEMMs: 64 rows/block, register-tiled 8 rows x 4 cols ----------------
// phase 1 smem: aspU[96][64f] (24K) | xspU[96][64f] (24K)  -- swizzled, packed row-pairs
// phase 2 smem: hsT[32 pairs][128] ull (32K) | wsTk[128][32] float (16K)
__global__ void __launch_bounds__(256) k_fused(
        const float* __restrict__ x,
        const float* __restrict__ W1l,
        const float* __restrict__ b1,
        const float* __restrict__ W1r,
        const float* __restrict__ W2l,
        const float* __restrict__ W2r) {

    __shared__ __align__(16) char sm[49152];
    float* aspF = reinterpret_cast<float*>(sm);                 // [96][64]
    float* xspF = aspF + 96 * 64;                               // [96][64]
    ull*   hsT  = reinterpret_cast<ull*>(sm);                   // [32][128]
    float* wsTk = reinterpret_cast<float*>(sm + 32768);         // [128][32]

    const int tid  = threadIdx.x;
    const int row0 = blockIdx.x * RB;

    // ---- staging: thread t -> row r = t>>2, k-chunk (t&3)*24; swizzle ull2-chunks mod 16
    {
        int r  = tid >> 2;
        int k0 = (tid & 3) * 24;
        int gnode = row0 + r;
        int q = r >> 2, lane = r & 3;
        if (gnode < NN) {
            float iv = 1.0f / fmaxf(g_zero[OFF_DEG + gnode], 1.0f);
            const float* pa = g_zero + OFF_AGG1 + (size_t)gnode * DIN + k0;
            const float* px = x + (size_t)gnode * DIN + k0;
#pragma unroll
            for (int i = 0; i < 24; i += 4) {
                float4 a4 = *(const float4*)(pa + i);
                float4 x4 = *(const float4*)(px + i);
#pragma unroll
                for (int kk = 0; kk < 4; kk++) {
                    int k = k0 + i + kk;
                    int pos = k * 64 + (((q + k) & 15) << 2) + lane;
                    aspF[pos] = ((const float*)&a4)[kk] * iv;
                    xspF[pos] = ((const float*)&x4)[kk];
                }
            }
        } else {
#pragma unroll
            for (int i = 0; i < 24; i++) {
                int k = k0 + i;
                int pos = k * 64 + (((q + k) & 15) << 2) + lane;
                aspF[pos] = 0.0f;
                xspF[pos] = 0.0f;
            }
        }
    }
    __syncthreads();

    // ---- stage A: thread (rg = tid>>5, cg = tid&31): rows 8rg..8rg+7, cols 4cg..4cg+3
    const int cg = tid & 31;
    const int rg = tid >> 5;

    ull acc[4][4];
    {
        float4 b4 = *(const float4*)(b1 + 4 * cg);
#pragma unroll
        for (int c = 0; c < 4; c++) {
            float bv = ((const float*)&b4)[c];
            ull bp = pk(bv, bv);
#pragma unroll
            for (int p = 0; p < 4; p++) acc[p][c] = bp;
        }
    }

    const ulonglong2* aU2 = (const ulonglong2*)aspF;   // [96][16]
    const ulonglong2* xU2 = (const ulonglong2*)xspF;

#pragma unroll 2
    for (int k = 0; k < DIN; k++) {
        int q0 = (2 * rg + k) & 15;
        int q1 = (2 * rg + 1 + k) & 15;
        ulonglong2 a01 = aU2[k * 16 + q0];   // pairs 4rg, 4rg+1
        ulonglong2 a23 = aU2[k * 16 + q1];   // pairs 4rg+2, 4rg+3
        ulonglong2 x01 = xU2[k * 16 + q0];
        ulonglong2 x23 = xU2[k * 16 + q1];
        float4 wl4 = __ldg((const float4*)(W1l + k * DH + 4 * cg));
        float4 wr4 = __ldg((const float4*)(W1r + k * DH + 4 * cg));
#pragma unroll
        for (int c = 0; c < 4; c++) {
            float wlv = ((const float*)&wl4)[c];
            float wrv = ((const float*)&wr4)[c];
            ull wl2 = pk(wlv, wlv);
            ull wr2 = pk(wrv, wrv);
            acc[0][c] = fma2(a01.x, wl2, acc[0][c]);
            acc[0][c] = fma2(x01.x, wr2, acc[0][c]);
            acc[1][c] = fma2(a01.y, wl2, acc[1][c]);
            acc[1][c] = fma2(x01.y, wr2, acc[1][c]);
            acc[2][c] = fma2(a23.x, wl2, acc[2][c]);
            acc[2][c] = fma2(x23.x, wr2, acc[2][c]);
            acc[3][c] = fma2(a23.y, wl2, acc[3][c]);
            acc[3][c] = fma2(x23.y, wr2, acc[3][c]);
        }
    }
    __syncthreads();   // asp/xsp reads complete before phase-2 overwrite

    // ---- relu + store h (packed pairs) + load W2 (k-major) ----
#pragma unroll
    for (int p = 0; p < 4; p++) {
        ulonglong2* dstp = (ulonglong2*)(hsT + (size_t)(4 * rg + p) * DH + 4 * cg);
        ulonglong2 v0, v1;
        v0.x = relu2(acc[p][0]); v0.y = relu2(acc[p][1]);
        v1.x = relu2(acc[p][2]); v1.y = relu2(acc[p][3]);
        dstp[0] = v0; dstp[1] = v1;
    }
    for (int i = tid; i < DH * DOUT; i += 256) {
        int k = i >> 4, j = i & 15;
        wsTk[k * 32 + j]      = W2l[i];
        wsTk[k * 32 + 16 + j] = W2r[i];
    }
    __syncthreads();

    // ---- stage B: thread (pg = tid>>4, c2 = tid&15): pairs {pg, pg+16}, cols {c2, c2+16}
    const int c2 = tid & 15;
    const int pg = tid >> 4;
    const ulonglong2* h0p = (const ulonglong2*)(hsT + (size_t)pg * DH);
    const ulonglong2* h1p = (const ulonglong2*)(hsT + (size_t)(pg + 16) * DH);

    ull a00 = 0, a01v = 0, a10 = 0, a11v = 0;
#pragma unroll 4
    for (int k4 = 0; k4 < DH / 4; k4++) {
        ulonglong2 hA0 = h0p[2 * k4], hA1 = h0p[2 * k4 + 1];
        ulonglong2 hB0 = h1p[2 * k4], hB1 = h1p[2 * k4 + 1];
#pragma unroll
        for (int kk = 0; kk < 4; kk++) {
            int k = 4 * k4 + kk;
            float w0 = wsTk[k * 32 + c2];
            float w1 = wsTk[k * 32 + 16 + c2];
            ull w0p = pk(w0, w0), w1p = pk(w1, w1);
            ull hA = (kk == 0) ? hA0.x : (kk == 1) ? hA0.y : (kk == 2) ? hA1.x : hA1.y;
            ull hB = (kk == 0) ? hB0.x : (kk == 1) ? hB0.y : (kk == 2) ? hB1.x : hB1.y;
            a00  = fma2(hA, w0p, a00);
            a01v = fma2(hA, w1p, a01v);
            a10  = fma2(hB, w0p, a10);
            a11v = fma2(hB, w1p, a11v);
        }
    }

    {
        int rA0 = row0 + 2 * pg,        rA1 = rA0 + 1;
        int rB0 = row0 + 2 * (pg + 16), rB1 = rB0 + 1;
        float2 f;
        f = upk(a00);
        if (rA0 < NN) g_r[(size_t)rA0 * 32 + c2] = f.x;
        if (rA1 < NN) g_r[(size_t)rA1 * 32 + c2] = f.y;
        f = upk(a01v);
        if (rA0 < NN) g_r[(size_t)rA0 * 32 + 16 + c2] = f.x;
        if (rA1 < NN) g_r[(size_t)rA1 * 32 + 16 + c2] = f.y;
        f = upk(a10);
        if (rB0 < NN) g_r[(size_t)rB0 * 32 + c2] = f.x;
        if (rB1 < NN) g_r[(size_t)rB1 * 32 + c2] = f.y;
        f = upk(a11v);
        if (rB0 < NN) g_r[(size_t)rB0 * 32 + 16 + c2] = f.x;
        if (rB1 < NN) g_r[(size_t)rB1 * 32 + 16 + c2] = f.y;
    }
}

// ---------------- layer-2 edge aggregation ----------------
__global__ void k_agg_p(const int* __restrict__ ei32,
                        const long long* __restrict__ ei64) {
    int gid = blockIdx.x * blockDim.x + threadIdx.x;
    if (gid >= NE * 4) return;
    int e = gid >> 2;
    int c = gid & 3;
    int src, dst;
    if (g_is64) { src = (int)ei64[e]; dst = (int)ei64[NE + e]; }
    else        { src = ei32[e];      dst = ei32[NE + e]; }

    const float4 v = ((const float4*)(g_r + (size_t)src * 32))[c];
    float4* o = ((float4*)(g_zero + OFF_AGG2 + (size_t)dst * DOUT)) + c;
    asm volatile("red.global.add.v4.f32 [%0], {%1,%2,%3,%4};"
                 :: "l"(o), "f"(v.x), "f"(v.y), "f"(v.z), "f"(v.w) : "memory");
}

// ---------------- epilogue: softmax(agg2/deg + b2 + q) ----------------
__global__ void k_finalize(const float* __restrict__ b2,
                           float* __restrict__ out) {
    int row = blockIdx.x * blockDim.x + threadIdx.x;
    if (row >= NN) return;
    float inv = 1.0f / fmaxf(g_zero[OFF_DEG + row], 1.0f);

    float v[DOUT];
    float mx = -1e30f;
#pragma unroll
    for (int j = 0; j < DOUT; j++) {
        v[j] = g_zero[OFF_AGG2 + (size_t)row * DOUT + j] * inv + b2[j]
             + g_r[(size_t)row * 32 + 16 + j];
        mx = fmaxf(mx, v[j]);
    }
    float s = 0.f;
#pragma unroll
    for (int j = 0; j < DOUT; j++) {
        v[j] = __expf(v[j] - mx);
        s += v[j];
    }
    float is = 1.0f / s;
#pragma unroll
    for (int j = 0; j < DOUT; j++)
        out[(size_t)row * DOUT + j] = v[j] * is;
}

// ---------------- launch ----------------
extern "C" void kernel_launch(void* const* d_in, const int* in_sizes, int n_in,
                              void* d_out, int out_size) {
    const float*     x    = (const float*)d_in[0];
    const int*       ei32 = (const int*)d_in[1];
    const long long* ei64 = (const long long*)d_in[1];
    const float*     W1l  = (const float*)d_in[2];
    const float*     b1   = (const float*)d_in[3];
    const float*     W1r  = (const float*)d_in[4];
    const float*     W2l  = (const float*)d_in[5];
    const float*     b2   = (const float*)d_in[6];
    const float*     W2r  = (const float*)d_in[7];
    float* out = (float*)d_out;

    void* zp;
    cudaGetSymbolAddress(&zp, g_zero);
    cudaMemsetAsync(zp, 0, sizeof(float) * ZTOTAL, 0);

    k_detect  <<<1, 32>>>(ei32);
    k_agg_x   <<<(NE * 24 + 255) / 256, 256>>>(ei32, ei64, x);
    k_fused   <<<(NN + RB - 1) / RB, 256>>>(x, W1l, b1, W1r, W2l, W2r);
    k_agg_p   <<<(NE * 4 + 255) / 256, 256>>>(ei32, ei64);
    k_finalize<<<(NN + 127) / 128, 128>>>(b2, out);
}